// round 6
// baseline (speedup 1.0000x reference)
#include <cuda_runtime.h>
#include <math_constants.h>

// Problem: B=32, T=2048, D=512, fp32
//   energy[b,t]    = dot(key[b,t,:], query[b,:])
//   attention[b,t] = softmax_T(energy)[b,t]
//   out[b,d]       = sum_t attention[b,t] * value[b,t,d]
// d_out layout: out (32*512 floats) then attention (32*2048 floats)

#define B 32
#define T 2048
#define D 512
#define TSPLIT 32
#define TCHUNK (T / TSPLIT)  // 64
#define ROWS_PER_WARP 8

// Scratch (no allocations allowed in kernel_launch)
__device__ float g_energy[B * T];

// ---------------------------------------------------------------------------
// Kernel 1: energy[b,t] = key[b,t,:] . query[b,:]
// One warp per 8 consecutive t-rows; q loaded into registers ONCE per warp.
// 36 LDG.128 per 8 rows (vs 64 before) -> frees LSU/L1tex for the k stream.
// ---------------------------------------------------------------------------
__global__ void energy_kernel(const float* __restrict__ query,
                              const float* __restrict__ key,
                              float* __restrict__ energy) {
    int gw = (blockIdx.x * blockDim.x + threadIdx.x) >> 5;  // 0..8191
    int lane = threadIdx.x & 31;
    int row0 = gw * ROWS_PER_WARP;      // global row = b*T + t, 8-aligned
    int b = row0 >> 11;                 // T = 2048

    const float4* qrow = (const float4*)(query + (size_t)b * D);
    float4 qv[4];
#pragma unroll
    for (int i = 0; i < 4; i++) qv[i] = qrow[lane + 32 * i];

    const float4* k0 = (const float4*)(key + (size_t)row0 * D);

#pragma unroll
    for (int r = 0; r < ROWS_PER_WARP; r++) {
        float4 kv[4];
#pragma unroll
        for (int i = 0; i < 4; i++)
            kv[i] = k0[(size_t)r * (D / 4) + lane + 32 * i];

        float acc = 0.0f;
#pragma unroll
        for (int i = 0; i < 4; i++)
            acc += kv[i].x * qv[i].x + kv[i].y * qv[i].y +
                   kv[i].z * qv[i].z + kv[i].w * qv[i].w;

#pragma unroll
        for (int off = 16; off; off >>= 1)
            acc += __shfl_xor_sync(0xFFFFFFFFu, acc, off);

        if (lane == 0) energy[row0 + r] = acc;
    }
}

// ---------------------------------------------------------------------------
// Kernel 2: softmax over T per batch. 32 blocks x 256 threads, 8 vals/thread.
// Shuffle-based reductions: 2 barriers instead of 16.
// ---------------------------------------------------------------------------
__global__ void softmax_kernel(const float* __restrict__ energy,
                               float* __restrict__ attn) {
    int b = blockIdx.x;
    int tid = threadIdx.x;      // 0..255
    int lane = tid & 31;
    int warp = tid >> 5;        // 0..7
    __shared__ float red[8];

    const float* e = energy + (size_t)b * T;
    float vals[8];
    float m = -CUDART_INF_F;
#pragma unroll
    for (int i = 0; i < 8; i++) {
        vals[i] = e[tid + 256 * i];
        m = fmaxf(m, vals[i]);
    }
#pragma unroll
    for (int off = 16; off; off >>= 1)
        m = fmaxf(m, __shfl_xor_sync(0xFFFFFFFFu, m, off));
    if (lane == 0) red[warp] = m;
    __syncthreads();
    m = red[0];
#pragma unroll
    for (int w = 1; w < 8; w++) m = fmaxf(m, red[w]);
    __syncthreads();

    float sum = 0.0f;
#pragma unroll
    for (int i = 0; i < 8; i++) {
        vals[i] = __expf(vals[i] - m);
        sum += vals[i];
    }
#pragma unroll
    for (int off = 16; off; off >>= 1)
        sum += __shfl_xor_sync(0xFFFFFFFFu, sum, off);
    if (lane == 0) red[warp] = sum;
    __syncthreads();
    sum = red[0];
#pragma unroll
    for (int w = 1; w < 8; w++) sum += red[w];
    float inv = 1.0f / sum;

    float* arow = attn + (size_t)b * T;
#pragma unroll
    for (int i = 0; i < 8; i++)
        arow[tid + 256 * i] = vals[i] * inv;
}

// ---------------------------------------------------------------------------
// Kernel 3: out[b,:] += sum_{t in chunk ts} attn[b,t] * value[b,t,:]
// Grid (TSPLIT, B) = 1024 blocks, 128 threads; thread owns one float4 of D.
// Accumulates directly into out via REDG.
// ---------------------------------------------------------------------------
__global__ void av_kernel(const float* __restrict__ attn,
                          const float* __restrict__ value,
                          float* __restrict__ out) {
    int ts = blockIdx.x;
    int b = blockIdx.y;
    int tid = threadIdx.x;  // 0..127

    __shared__ float sa[TCHUNK];
    int t0 = ts * TCHUNK;
    if (tid < TCHUNK) sa[tid] = attn[(size_t)b * T + t0 + tid];
    __syncthreads();

    const float4* v = (const float4*)(value + ((size_t)b * T + t0) * D);
    float4 acc = make_float4(0.f, 0.f, 0.f, 0.f);

#pragma unroll 8
    for (int t = 0; t < TCHUNK; t++) {
        float a = sa[t];
        float4 vv = v[(size_t)t * (D / 4) + tid];
        acc.x += a * vv.x;
        acc.y += a * vv.y;
        acc.z += a * vv.z;
        acc.w += a * vv.w;
    }

    float* o = out + (size_t)b * D + tid * 4;
    atomicAdd(o + 0, acc.x);
    atomicAdd(o + 1, acc.y);
    atomicAdd(o + 2, acc.z);
    atomicAdd(o + 3, acc.w);
}

extern "C" void kernel_launch(void* const* d_in, const int* in_sizes, int n_in,
                              void* d_out, int out_size) {
    const float* query = (const float*)d_in[0];  // [B, D]
    const float* key   = (const float*)d_in[1];  // [B, T, D]
    const float* value = (const float*)d_in[2];  // [B, T, D]

    float* out  = (float*)d_out;            // [B, D]
    float* attn = (float*)d_out + B * D;    // [B, T]

    float* energy;
    cudaGetSymbolAddress((void**)&energy, g_energy);

    // Zero the out slice (memset node — graph-capturable, no allocation).
    cudaMemsetAsync(out, 0, (size_t)B * D * sizeof(float), 0);

    // 1) energy: 8192 warps, 8 rows each
    energy_kernel<<<(B * T / ROWS_PER_WARP) / 8, 256>>>(query, key, energy);
    // 2) softmax -> attention slice of d_out
    softmax_kernel<<<B, 256>>>(energy, attn);
    // 3) attn @ value, accumulated straight into out
    {
        dim3 grid(TSPLIT, B);
        av_kernel<<<grid, 128>>>(attn, value, out);
    }
}

// round 7
// speedup vs baseline: 1.0219x; 1.0219x over previous
#include <cuda_runtime.h>
#include <math_constants.h>

// Problem: B=32, T=2048, D=512, fp32
//   energy[b,t]    = dot(key[b,t,:], query[b,:])
//   attention[b,t] = softmax_T(energy)[b,t]
//   out[b,d]       = sum_t attention[b,t] * value[b,t,d]
// d_out layout: out (32*512 floats) then attention (32*2048 floats)

#define B 32
#define T 2048
#define D 512
#define TSPLIT 32
#define TCHUNK (T / TSPLIT)   // 64
#define EROWS 64              // energy rows per block

// Scratch (no allocations allowed in kernel_launch)
__device__ float g_energy[B * T];

// ---------------------------------------------------------------------------
// Kernel 1: energy[b,t] = key[b,t,:] . query[b,:]
// Block = 256 thr (8 warps) handles 64 consecutive rows (same batch, since
// T=2048 is a multiple of 64). Each warp streams 8 rows with NO cross-lane
// dependency in the load loop: lane keeps 8 private partials (32 independent
// LDG.128 -> deep MLP). Reduction happens afterwards from padded smem.
// ---------------------------------------------------------------------------
__global__ void energy_kernel(const float* __restrict__ query,
                              const float* __restrict__ key,
                              float* __restrict__ energy) {
    int blk = blockIdx.x;            // 0..1023
    int row0 = blk * EROWS;          // global row = b*T + t
    int b = row0 >> 11;              // T = 2048
    int tid = threadIdx.x;
    int lane = tid & 31;
    int warp = tid >> 5;             // 0..7

    __shared__ float part[EROWS][33];  // stride-33 pad: conflict-free col sums

    const float4* qrow = (const float4*)(query + (size_t)b * D);
    float4 qv[4];
#pragma unroll
    for (int i = 0; i < 4; i++) qv[i] = qrow[lane + 32 * i];

    const float4* k0 = (const float4*)(key + (size_t)(row0 + warp * 8) * D);

    float acc[8];
#pragma unroll
    for (int r = 0; r < 8; r++) {
        float4 kv[4];
#pragma unroll
        for (int i = 0; i < 4; i++)
            kv[i] = k0[(size_t)r * (D / 4) + lane + 32 * i];
        acc[r] = kv[0].x * qv[0].x + kv[0].y * qv[0].y + kv[0].z * qv[0].z + kv[0].w * qv[0].w
               + kv[1].x * qv[1].x + kv[1].y * qv[1].y + kv[1].z * qv[1].z + kv[1].w * qv[1].w
               + kv[2].x * qv[2].x + kv[2].y * qv[2].y + kv[2].z * qv[2].z + kv[2].w * qv[2].w
               + kv[3].x * qv[3].x + kv[3].y * qv[3].y + kv[3].z * qv[3].z + kv[3].w * qv[3].w;
    }

#pragma unroll
    for (int r = 0; r < 8; r++)
        part[warp * 8 + r][lane] = acc[r];
    __syncthreads();

    if (tid < EROWS) {
        float s = 0.0f;
#pragma unroll
        for (int i = 0; i < 32; i++)
            s += part[tid][i];
        energy[row0 + tid] = s;
    }
}

// ---------------------------------------------------------------------------
// Kernel 2: softmax over T per batch. 32 blocks x 256 threads, 8 vals/thread.
// Shuffle-based reductions: 2 barriers total.
// ---------------------------------------------------------------------------
__global__ void softmax_kernel(const float* __restrict__ energy,
                               float* __restrict__ attn) {
    int b = blockIdx.x;
    int tid = threadIdx.x;      // 0..255
    int lane = tid & 31;
    int warp = tid >> 5;        // 0..7
    __shared__ float red[8];

    const float* e = energy + (size_t)b * T;
    float vals[8];
    float m = -CUDART_INF_F;
#pragma unroll
    for (int i = 0; i < 8; i++) {
        vals[i] = e[tid + 256 * i];
        m = fmaxf(m, vals[i]);
    }
#pragma unroll
    for (int off = 16; off; off >>= 1)
        m = fmaxf(m, __shfl_xor_sync(0xFFFFFFFFu, m, off));
    if (lane == 0) red[warp] = m;
    __syncthreads();
    m = red[0];
#pragma unroll
    for (int w = 1; w < 8; w++) m = fmaxf(m, red[w]);
    __syncthreads();

    float sum = 0.0f;
#pragma unroll
    for (int i = 0; i < 8; i++) {
        vals[i] = __expf(vals[i] - m);
        sum += vals[i];
    }
#pragma unroll
    for (int off = 16; off; off >>= 1)
        sum += __shfl_xor_sync(0xFFFFFFFFu, sum, off);
    if (lane == 0) red[warp] = sum;
    __syncthreads();
    sum = red[0];
#pragma unroll
    for (int w = 1; w < 8; w++) sum += red[w];
    float inv = 1.0f / sum;

    float* arow = attn + (size_t)b * T;
#pragma unroll
    for (int i = 0; i < 8; i++)
        arow[tid + 256 * i] = vals[i] * inv;
}

// ---------------------------------------------------------------------------
// Kernel 3: out[b,:] += sum_{t in chunk ts} attn[b,t] * value[b,t,:]
// Grid (TSPLIT, B) = 1024 blocks, 128 threads; thread owns one float4 of D.
// Accumulates directly into out via REDG.
// ---------------------------------------------------------------------------
__global__ void av_kernel(const float* __restrict__ attn,
                          const float* __restrict__ value,
                          float* __restrict__ out) {
    int ts = blockIdx.x;
    int b = blockIdx.y;
    int tid = threadIdx.x;  // 0..127

    __shared__ float sa[TCHUNK];
    int t0 = ts * TCHUNK;
    if (tid < TCHUNK) sa[tid] = attn[(size_t)b * T + t0 + tid];
    __syncthreads();

    const float4* v = (const float4*)(value + ((size_t)b * T + t0) * D);
    float4 acc = make_float4(0.f, 0.f, 0.f, 0.f);

#pragma unroll 8
    for (int t = 0; t < TCHUNK; t++) {
        float a = sa[t];
        float4 vv = v[(size_t)t * (D / 4) + tid];
        acc.x += a * vv.x;
        acc.y += a * vv.y;
        acc.z += a * vv.z;
        acc.w += a * vv.w;
    }

    float* o = out + (size_t)b * D + tid * 4;
    atomicAdd(o + 0, acc.x);
    atomicAdd(o + 1, acc.y);
    atomicAdd(o + 2, acc.z);
    atomicAdd(o + 3, acc.w);
}

extern "C" void kernel_launch(void* const* d_in, const int* in_sizes, int n_in,
                              void* d_out, int out_size) {
    const float* query = (const float*)d_in[0];  // [B, D]
    const float* key   = (const float*)d_in[1];  // [B, T, D]
    const float* value = (const float*)d_in[2];  // [B, T, D]

    float* out  = (float*)d_out;            // [B, D]
    float* attn = (float*)d_out + B * D;    // [B, T]

    float* energy;
    cudaGetSymbolAddress((void**)&energy, g_energy);

    // Zero the out slice (memset node — graph-capturable, no allocation).
    cudaMemsetAsync(out, 0, (size_t)B * D * sizeof(float), 0);

    // 1) energy: 1024 blocks x 256 thr, 64 rows/block
    energy_kernel<<<(B * T) / EROWS, 256>>>(query, key, energy);
    // 2) softmax -> attention slice of d_out
    softmax_kernel<<<B, 256>>>(energy, attn);
    // 3) attn @ value, accumulated straight into out
    {
        dim3 grid(TSPLIT, B);
        av_kernel<<<grid, 128>>>(attn, value, out);
    }
}